// round 12
// baseline (speedup 1.0000x reference)
#include <cuda_runtime.h>
#include <cuda_fp16.h>
#include <math.h>

#define N_NODES 100000
#define E_EDGES 1600000
#define IN_DIM  128
#define HEADS   8
#define HID     16
#define OUT_DIM 128
#define NEG_SLOPE 0.2f
#define CAP     64            // padded-CSR slots per row (P[deg>64] < 1e-15)
#define CAP_LOG 6
#define GEMM_GROUPS ((N_NODES + 127) / 128)           // 782
#define A_PITCH 68            // A smem pitch in b32 words (bank = 4*m0+t, conflict-free)

// ---- scratch (static device globals; no runtime allocation) ----
__device__ __align__(16) __half g_h16[(size_t)N_NODES * OUT_DIM]; // 25.6 MB
__device__ float g_al[N_NODES * HEADS];                 // 3.2 MB
__device__ float g_ar[N_NODES * HEADS];                 // 3.2 MB
__device__ int   g_deg[N_NODES];
__device__ __align__(16) int g_rel[E_EDGES];            // 6.4 MB in-row position
__device__ int   g_csr_col[(size_t)N_NODES * CAP];      // 25.6 MB padded CSR
__device__ __align__(16) uint2 g_bfrag16[16 * 8 * 32];  // 32 KB: W16 in m16n8k16 B-frag order

// ------------------------------------------------------------------
// Degree histogram; returned old count = edge's slot within its row
// (the only atomic pass of the CSR build).
// ------------------------------------------------------------------
__global__ void hist_kernel(const int* __restrict__ ei) {
    const int4* r4 = (const int4*)ei;
    int4* rel4 = (int4*)g_rel;
    int stride = gridDim.x * blockDim.x;
    for (int i = blockIdx.x * blockDim.x + threadIdx.x; i < E_EDGES / 4; i += stride) {
        int4 r = r4[i];
        int4 p;
        p.x = atomicAdd(&g_deg[r.x], 1);
        p.y = atomicAdd(&g_deg[r.y], 1);
        p.z = atomicAdd(&g_deg[r.z], 1);
        p.w = atomicAdd(&g_deg[r.w], 1);
        rel4[i] = p;
    }
}

// ------------------------------------------------------------------
// Scatter into padded CSR: csr[row*CAP + rel] = col.
// ------------------------------------------------------------------
__global__ void scatter_kernel(const int* __restrict__ ei) {
    const int4* r4   = (const int4*)ei;
    const int4* c4   = (const int4*)(ei + E_EDGES);
    const int4* rel4 = (const int4*)g_rel;
    int stride = gridDim.x * blockDim.x;
    for (int i = blockIdx.x * blockDim.x + threadIdx.x; i < E_EDGES / 4; i += stride) {
        int4 r = r4[i];
        int4 c = c4[i];
        int4 p = rel4[i];
        if (p.x < CAP) g_csr_col[((size_t)r.x << CAP_LOG) + p.x] = c.x;
        if (p.y < CAP) g_csr_col[((size_t)r.y << CAP_LOG) + p.y] = c.y;
        if (p.z < CAP) g_csr_col[((size_t)r.z << CAP_LOG) + p.z] = c.z;
        if (p.w < CAP) g_csr_col[((size_t)r.w << CAP_LOG) + p.w] = c.w;
    }
}

// ------------------------------------------------------------------
// Build W (fp16) into mma.m16n8k16 B-fragment order, once.
// flat = (nt*8 + ks)*32 + lane ; g = lane>>2, t = lane&3
// b0 = W16[nt*8+g][ks*16 + 2t, +1], b1 = W16[...][ks*16 + 2t+8, +9]
// ------------------------------------------------------------------
__global__ void bfrag_build_kernel(const float* __restrict__ W) {
    int flat = blockIdx.x * blockDim.x + threadIdx.x;
    if (flat >= 16 * 8 * 32) return;
    int lane = flat & 31;
    int ks   = (flat >> 5) & 7;
    int nt   = flat >> 8;
    int n  = nt * 8 + (lane >> 2);
    int k0 = ks * 16 + 2 * (lane & 3);
    const float* Wr = W + n * IN_DIM;
    __half2 b0 = __floats2half2_rn(Wr[k0],     Wr[k0 + 1]);
    __half2 b1 = __floats2half2_rn(Wr[k0 + 8], Wr[k0 + 9]);
    g_bfrag16[flat] = make_uint2(*(unsigned*)&b0, *(unsigned*)&b1);
}

// ------------------------------------------------------------------
// h16 = (x @ W^T) via fp16 mma.m16n8k16 (fp32 accum), al/ar fused in
// the epilogue. A: CTA stages 128 x-rows into fp16 SMEM (float4 LDG +
// convert; pitch A_PITCH words -> conflict-free frag LDS.32).
// B: 32 KB prebuilt fragments in SMEM. 2 CTAs/SM.
// ------------------------------------------------------------------
__global__ void __launch_bounds__(256, 2)
gemm_kernel(const float* __restrict__ x, const float* __restrict__ att) {
    extern __shared__ char smem[];
    uint2*    Bs    = (uint2*)smem;                          // 4096 uint2 = 32 KB
    unsigned* As    = (unsigned*)(smem + 32768);             // 128 * A_PITCH words
    float*    sAttL = (float*)(smem + 32768 + 128 * A_PITCH * 4);
    float*    sAttR = sAttL + 128;

    const int tid = threadIdx.x;
    const int w   = tid >> 5;
    const int l   = tid & 31;
    const int cta_node0 = blockIdx.x * 128;

    // Copy B fragments (32 KB) coalesced.
    {
        const float4* src = (const float4*)g_bfrag16;
        float4* dst = (float4*)Bs;
        for (int i = tid; i < 2048; i += 256) dst[i] = src[i];
        if (tid < 128) {
            int hd = tid >> 4, d = tid & 15;
            sAttL[tid] = att[hd * (2 * HID) + d];
            sAttR[tid] = att[hd * (2 * HID) + HID + d];
        }
    }

    // Stage 128 x-rows as fp16 into SMEM (convert in flight).
    for (int i = tid; i < 4096; i += 256) {
        int r  = i >> 5;           // row 0..127
        int sg = i & 31;           // float4 segment
        int row = cta_node0 + r;
        if (row >= N_NODES) row = N_NODES - 1;     // clamp; results discarded
        float4 v = *(const float4*)&x[(size_t)row * IN_DIM + 4 * sg];
        __half2 h0 = __floats2half2_rn(v.x, v.y);
        __half2 h1 = __floats2half2_rn(v.z, v.w);
        *(uint2*)&As[r * A_PITCH + 2 * sg] =
            make_uint2(*(unsigned*)&h0, *(unsigned*)&h1);
    }
    __syncthreads();

    const int node0 = cta_node0 + w * 16;
    if (node0 >= N_NODES) return;   // warp-uniform; no CTA sync below

    const int m0 = l >> 2;     // 0..7
    const int cg = l & 3;      // 0..3
    const unsigned* ArowA = As + (w * 16 + m0) * A_PITCH;
    const unsigned* ArowB = ArowA + 8 * A_PITCH;

    float c[16][4];
#pragma unroll
    for (int nt = 0; nt < 16; nt++)
#pragma unroll
        for (int j = 0; j < 4; j++) c[nt][j] = 0.0f;

#pragma unroll
    for (int ks = 0; ks < 8; ks++) {
        unsigned a0 = ArowA[ks * 8 + cg];        // (m0,   k 2cg..+1)
        unsigned a1 = ArowB[ks * 8 + cg];        // (m0+8, k 2cg..+1)
        unsigned a2 = ArowA[ks * 8 + cg + 4];    // (m0,   k 2cg+8..+9)
        unsigned a3 = ArowB[ks * 8 + cg + 4];    // (m0+8, k 2cg+8..+9)
#pragma unroll
        for (int nt = 0; nt < 16; nt++) {
            uint2 b = Bs[(nt * 8 + ks) * 32 + l];
            asm volatile(
                "mma.sync.aligned.m16n8k16.row.col.f32.f16.f16.f32 "
                "{%0,%1,%2,%3}, {%4,%5,%6,%7}, {%8,%9}, {%0,%1,%2,%3};"
                : "+f"(c[nt][0]), "+f"(c[nt][1]), "+f"(c[nt][2]), "+f"(c[nt][3])
                : "r"(a0), "r"(a1), "r"(a2), "r"(a3), "r"(b.x), "r"(b.y));
        }
    }

    // Epilogue: h16 stores + fused al/ar (D layout: c0,c1 = row m0 cols
    // 2cg..+1; c2,c3 = row m0+8 — identical to the verified tf32 path).
#pragma unroll
    for (int pass = 0; pass < 2; pass++) {
        const int row = node0 + m0 + pass * 8;
        const int j0 = pass * 2;
        float sl[8], sr[8];
#pragma unroll
        for (int h = 0; h < 8; h++) { sl[h] = 0.f; sr[h] = 0.f; }
#pragma unroll
        for (int nt = 0; nt < 16; nt++) {
            int col = nt * 8 + 2 * cg;
            __half2 hp = __floats2half2_rn(c[nt][j0], c[nt][j0 + 1]);
            *(__half2*)&g_h16[(size_t)row * OUT_DIM + col] = hp;
            float2 la = *(float2*)&sAttL[col];
            float2 ra = *(float2*)&sAttR[col];
            int h = nt >> 1;
            sl[h] += c[nt][j0] * la.x + c[nt][j0 + 1] * la.y;
            sr[h] += c[nt][j0] * ra.x + c[nt][j0 + 1] * ra.y;
        }
#pragma unroll
        for (int h = 0; h < 8; h++) {
            sl[h] += __shfl_xor_sync(0xffffffffu, sl[h], 1);
            sr[h] += __shfl_xor_sync(0xffffffffu, sr[h], 1);
            sl[h] += __shfl_xor_sync(0xffffffffu, sl[h], 2);
            sr[h] += __shfl_xor_sync(0xffffffffu, sr[h], 2);
        }
        if (cg == 0) {
            *(float4*)&g_al[row * HEADS]     = make_float4(sl[0], sl[1], sl[2], sl[3]);
            *(float4*)&g_al[row * HEADS + 4] = make_float4(sl[4], sl[5], sl[6], sl[7]);
            *(float4*)&g_ar[row * HEADS]     = make_float4(sr[0], sr[1], sr[2], sr[3]);
            *(float4*)&g_ar[row * HEADS + 4] = make_float4(sr[4], sr[5], sr[6], sr[7]);
        }
    }
}

// ------------------------------------------------------------------
// Gather: HALF-WARP per row (two independent chains per warp).
// Phase-1: 32 lanes compute alpha for 4 nbrs x 8 heads of row0,
// then row1; phase-2: lane l16 owns cols 8*l16..+7 of its half's
// row, 4 predicated LDG.128 per step. No atomics, no reductions.
// Padded CSR: beg = row<<6, end = deg[row].
// ------------------------------------------------------------------
__global__ void __launch_bounds__(256)
gather_kernel(const float* __restrict__ pos, float* __restrict__ out) {
    const int l   = threadIdx.x & 31;
    const int p   = l >> 4;         // half-warp -> row select
    const int l16 = l & 15;
    const int hd2 = l16 >> 1;       // head for this lane's 8 cols
    const int nb  = l >> 3;         // phase-1 neighbor slot (0..3)
    const int hp  = l & 7;          // phase-1 head (0..7)
    int warp = (blockIdx.x * blockDim.x + threadIdx.x) >> 5;
    if (warp >= N_NODES / 2) return;

    const int row0 = warp * 2;
    const int row1 = row0 + 1;
    const int myrow = p ? row1 : row0;

    int deg0 = min(g_deg[row0], CAP);
    int deg1 = min(g_deg[row1], CAP);
    const int beg0 = row0 << CAP_LOG;
    const int beg1 = row1 << CAP_LOG;
    float alr0 = g_al[row0 * HEADS + hp];
    float alr1 = g_al[row1 * HEADS + hp];

    float4 accA = make_float4(0.f, 0.f, 0.f, 0.f);
    float4 accB = make_float4(0.f, 0.f, 0.f, 0.f);
    float s = 0.f;
    const int steps = max(deg0, deg1);

    for (int base = 0; base < steps; base += 4) {
        int j = base + nb;
        int c0 = (j < deg0) ? g_csr_col[beg0 + j] : 0;
        int c1 = (j < deg1) ? g_csr_col[beg1 + j] : 0;
        float ar0 = g_ar[c0 * HEADS + hp];
        float ar1 = g_ar[c1 * HEADS + hp];
        float p0 = pos[c0];
        float p1 = pos[c1];

        float t0 = alr0 + ar0;
        t0 = (t0 >= 0.0f) ? t0 : NEG_SLOPE * t0;
        float a0 = (j < deg0) ? __expf(t0) * p0 : 0.0f;
        float t1 = alr1 + ar1;
        t1 = (t1 >= 0.0f) ? t1 : NEG_SLOPE * t1;
        float a1 = (j < deg1) ? __expf(t1) * p1 : 0.0f;

        float aq[4]; int cq[4];
#pragma unroll
        for (int k = 0; k < 4; k++) {
            float aa0 = __shfl_sync(0xffffffffu, a0, k * 8 + hd2);
            int   cc0 = __shfl_sync(0xffffffffu, c0, k * 8);
            float aa1 = __shfl_sync(0xffffffffu, a1, k * 8 + hd2);
            int   cc1 = __shfl_sync(0xffffffffu, c1, k * 8);
            aq[k] = p ? aa1 : aa0;
            cq[k] = p ? cc1 : cc0;
        }

        uint4 hv[4];
#pragma unroll
        for (int k = 0; k < 4; k++) {
            if (aq[k] != 0.0f)
                hv[k] = *(const uint4*)&g_h16[(size_t)cq[k] * OUT_DIM + 8 * l16];
            else
                hv[k] = make_uint4(0, 0, 0, 0);
        }
#pragma unroll
        for (int k = 0; k < 4; k++) {
            const __half2* h2p = (const __half2*)&hv[k];
            float2 f0 = __half22float2(h2p[0]);
            float2 f1 = __half22float2(h2p[1]);
            float2 f2 = __half22float2(h2p[2]);
            float2 f3 = __half22float2(h2p[3]);
            s += aq[k];
            accA.x += aq[k] * f0.x;
            accA.y += aq[k] * f0.y;
            accA.z += aq[k] * f1.x;
            accA.w += aq[k] * f1.y;
            accB.x += aq[k] * f2.x;
            accB.y += aq[k] * f2.y;
            accB.z += aq[k] * f3.x;
            accB.w += aq[k] * f3.y;
        }
    }

    int mydeg = p ? deg1 : deg0;
    float scale = (mydeg > 0) ? (1.0f / s + 1e-16f) : 0.0f;
    accA.x *= scale; accA.y *= scale; accA.z *= scale; accA.w *= scale;
    accB.x *= scale; accB.y *= scale; accB.z *= scale; accB.w *= scale;
    *(float4*)&out[(size_t)myrow * OUT_DIM + 8 * l16]     = accA;
    *(float4*)&out[(size_t)myrow * OUT_DIM + 8 * l16 + 4] = accB;
}

// ------------------------------------------------------------------
// Side stream + fork/join events (host-side resources, created once
// on the first non-capturing invocation).
// ------------------------------------------------------------------
struct SideStream {
    cudaStream_t s;
    cudaEvent_t fork, join;
    SideStream() {
        cudaStreamCreateWithFlags(&s, cudaStreamNonBlocking);
        cudaEventCreateWithFlags(&fork, cudaEventDisableTiming);
        cudaEventCreateWithFlags(&join, cudaEventDisableTiming);
    }
};
static SideStream& side() { static SideStream ss; return ss; }

extern "C" void kernel_launch(void* const* d_in, const int* in_sizes, int n_in,
                              void* d_out, int out_size) {
    const float* x   = (const float*)d_in[0];   // (N, 128)
    const int*   ei  = (const int*)d_in[1];     // (2, E)
    const float* pos = (const float*)d_in[2];   // (N,)
    const float* W   = (const float*)d_in[3];   // (128, 128)
    const float* att = (const float*)d_in[4];   // (1, 8, 32)
    float* out = (float*)d_out;

    SideStream& ss = side();

    // Fork: padded-CSR build on side stream; GEMM branch on origin.
    cudaEventRecord(ss.fork, 0);
    cudaStreamWaitEvent(ss.s, ss.fork, 0);

    void* degp = nullptr;
    cudaGetSymbolAddress(&degp, g_deg);
    cudaMemsetAsync(degp, 0, N_NODES * sizeof(int), ss.s);
    hist_kernel<<<1024, 256, 0, ss.s>>>(ei);
    scatter_kernel<<<1600, 256, 0, ss.s>>>(ei);
    cudaEventRecord(ss.join, ss.s);

    bfrag_build_kernel<<<16, 256>>>(W);
    const int GEMM_SMEM = 32768 + 128 * A_PITCH * 4 + 1024;   // 68608 B
    cudaFuncSetAttribute(gemm_kernel, cudaFuncAttributeMaxDynamicSharedMemorySize, GEMM_SMEM);
    gemm_kernel<<<GEMM_GROUPS, 256, GEMM_SMEM>>>(x, att);

    // Join, then fused softmax-normalized aggregation (atomic-free).
    cudaStreamWaitEvent(0, ss.join, 0);
    gather_kernel<<<(N_NODES / 2 + 7) / 8, 256>>>(pos, out);
}

// round 16
// speedup vs baseline: 1.0172x; 1.0172x over previous
#include <cuda_runtime.h>
#include <cuda_fp16.h>
#include <math.h>

#define N_NODES 100000
#define E_EDGES 1600000
#define IN_DIM  128
#define HEADS   8
#define HID     16
#define OUT_DIM 128
#define NEG_SLOPE 0.2f
#define CAP     64            // padded-CSR slots per row (P[deg>64] < 1e-15)
#define CAP_LOG 6
#define GEMM_GROUPS ((N_NODES + 63) / 64)   // 1563 CTAs, 64 rows each
#define A_PITCH 68            // A smem pitch in b32 words (bank = 4*m0+cg, conflict-free)

// ---- scratch (static device globals; no runtime allocation) ----
__device__ __align__(16) __half g_h16[(size_t)N_NODES * OUT_DIM]; // 25.6 MB
__device__ float g_al[N_NODES * HEADS];                 // 3.2 MB
__device__ float g_ar[N_NODES * HEADS];                 // 3.2 MB
__device__ int   g_deg[N_NODES];
__device__ __align__(16) int g_rel[E_EDGES];            // 6.4 MB in-row position
__device__ int   g_csr_col[(size_t)N_NODES * CAP];      // 25.6 MB padded CSR
__device__ __align__(16) uint2 g_bfrag16[16 * 8 * 32];  // 32 KB: W16 in m16n8k16 B-frag order

// ------------------------------------------------------------------
// Degree histogram; returned old count = edge's slot within its row
// (the only atomic pass of the CSR build).
// ------------------------------------------------------------------
__global__ void hist_kernel(const int* __restrict__ ei) {
    const int4* r4 = (const int4*)ei;
    int4* rel4 = (int4*)g_rel;
    int stride = gridDim.x * blockDim.x;
    for (int i = blockIdx.x * blockDim.x + threadIdx.x; i < E_EDGES / 4; i += stride) {
        int4 r = r4[i];
        int4 p;
        p.x = atomicAdd(&g_deg[r.x], 1);
        p.y = atomicAdd(&g_deg[r.y], 1);
        p.z = atomicAdd(&g_deg[r.z], 1);
        p.w = atomicAdd(&g_deg[r.w], 1);
        rel4[i] = p;
    }
}

// ------------------------------------------------------------------
// Scatter into padded CSR: csr[row*CAP + rel] = col.
// ------------------------------------------------------------------
__global__ void scatter_kernel(const int* __restrict__ ei) {
    const int4* r4   = (const int4*)ei;
    const int4* c4   = (const int4*)(ei + E_EDGES);
    const int4* rel4 = (const int4*)g_rel;
    int stride = gridDim.x * blockDim.x;
    for (int i = blockIdx.x * blockDim.x + threadIdx.x; i < E_EDGES / 4; i += stride) {
        int4 r = r4[i];
        int4 c = c4[i];
        int4 p = rel4[i];
        if (p.x < CAP) g_csr_col[((size_t)r.x << CAP_LOG) + p.x] = c.x;
        if (p.y < CAP) g_csr_col[((size_t)r.y << CAP_LOG) + p.y] = c.y;
        if (p.z < CAP) g_csr_col[((size_t)r.z << CAP_LOG) + p.z] = c.z;
        if (p.w < CAP) g_csr_col[((size_t)r.w << CAP_LOG) + p.w] = c.w;
    }
}

// ------------------------------------------------------------------
// Build W (fp16) into mma.m16n8k16 B-fragment order, once.
// ------------------------------------------------------------------
__global__ void bfrag_build_kernel(const float* __restrict__ W) {
    int flat = blockIdx.x * blockDim.x + threadIdx.x;
    if (flat >= 16 * 8 * 32) return;
    int lane = flat & 31;
    int ks   = (flat >> 5) & 7;
    int nt   = flat >> 8;
    int n  = nt * 8 + (lane >> 2);
    int k0 = ks * 16 + 2 * (lane & 3);
    const float* Wr = W + n * IN_DIM;
    __half2 b0 = __floats2half2_rn(Wr[k0],     Wr[k0 + 1]);
    __half2 b1 = __floats2half2_rn(Wr[k0 + 8], Wr[k0 + 9]);
    g_bfrag16[flat] = make_uint2(*(unsigned*)&b0, *(unsigned*)&b1);
}

// ------------------------------------------------------------------
// h16 = (x @ W^T) via fp16 mma.m16n8k16 (fp32 accum), al/ar fused.
// Warp tile 16x64: warp w -> rows (w&3)*16, cols (w>>2)*64. CTA =
// 64 rows x 128 cols. SMEM = B frags 32 KB + A 17 KB -> 3 CTAs/SM.
// Heads 4*wcol..+3 live entirely in this warp's column half, so the
// fused al/ar needs no cross-warp reduction.
// ------------------------------------------------------------------
__global__ void __launch_bounds__(256, 3)
gemm_kernel(const float* __restrict__ x, const float* __restrict__ att) {
    extern __shared__ char smem[];
    uint2*    Bs    = (uint2*)smem;                          // 4096 uint2 = 32 KB
    unsigned* As    = (unsigned*)(smem + 32768);             // 64 * A_PITCH words
    float*    sAttL = (float*)(smem + 32768 + 64 * A_PITCH * 4);
    float*    sAttR = sAttL + 128;

    const int tid = threadIdx.x;
    const int w   = tid >> 5;
    const int l   = tid & 31;
    const int cta_node0 = blockIdx.x * 64;

    // Copy B fragments (32 KB) coalesced + att to smem.
    {
        const float4* src = (const float4*)g_bfrag16;
        float4* dst = (float4*)Bs;
        for (int i = tid; i < 2048; i += 256) dst[i] = src[i];
        if (tid < 128) {
            int hd = tid >> 4, d = tid & 15;
            sAttL[tid] = att[hd * (2 * HID) + d];
            sAttR[tid] = att[hd * (2 * HID) + HID + d];
        }
    }

    // Stage 64 x-rows as fp16 into SMEM (convert in flight).
    for (int i = tid; i < 2048; i += 256) {
        int r  = i >> 5;           // row 0..63
        int sg = i & 31;           // float4 segment
        int row = cta_node0 + r;
        if (row >= N_NODES) row = N_NODES - 1;     // clamp; results discarded
        float4 v = *(const float4*)&x[(size_t)row * IN_DIM + 4 * sg];
        __half2 h0 = __floats2half2_rn(v.x, v.y);
        __half2 h1 = __floats2half2_rn(v.z, v.w);
        *(uint2*)&As[r * A_PITCH + 2 * sg] =
            make_uint2(*(unsigned*)&h0, *(unsigned*)&h1);
    }
    __syncthreads();

    const int wrow = w & 3;        // row group (0..3)
    const int wcol = w >> 2;       // column half (0..1)
    const int node0 = cta_node0 + wrow * 16;
    if (node0 >= N_NODES) return;  // N % 16 == 0, so no partial warps

    const int m0 = l >> 2;     // 0..7
    const int cg = l & 3;      // 0..3
    const unsigned* ArowA = As + (wrow * 16 + m0) * A_PITCH;
    const unsigned* ArowB = ArowA + 8 * A_PITCH;

    float c[8][4];
#pragma unroll
    for (int nt = 0; nt < 8; nt++)
#pragma unroll
        for (int j = 0; j < 4; j++) c[nt][j] = 0.0f;

#pragma unroll
    for (int ks = 0; ks < 8; ks++) {
        unsigned a0 = ArowA[ks * 8 + cg];
        unsigned a1 = ArowB[ks * 8 + cg];
        unsigned a2 = ArowA[ks * 8 + cg + 4];
        unsigned a3 = ArowB[ks * 8 + cg + 4];
#pragma unroll
        for (int nt = 0; nt < 8; nt++) {
            uint2 b = Bs[((wcol * 8 + nt) * 8 + ks) * 32 + l];
            asm volatile(
                "mma.sync.aligned.m16n8k16.row.col.f32.f16.f16.f32 "
                "{%0,%1,%2,%3}, {%4,%5,%6,%7}, {%8,%9}, {%0,%1,%2,%3};"
                : "+f"(c[nt][0]), "+f"(c[nt][1]), "+f"(c[nt][2]), "+f"(c[nt][3])
                : "r"(a0), "r"(a1), "r"(a2), "r"(a3), "r"(b.x), "r"(b.y));
        }
    }

    // Epilogue: h16 stores + fused al/ar for heads 4*wcol..+3.
#pragma unroll
    for (int pass = 0; pass < 2; pass++) {
        const int row = node0 + m0 + pass * 8;
        const int j0 = pass * 2;
        float sl[4], sr[4];
#pragma unroll
        for (int h = 0; h < 4; h++) { sl[h] = 0.f; sr[h] = 0.f; }
#pragma unroll
        for (int nt = 0; nt < 8; nt++) {
            int col = wcol * 64 + nt * 8 + 2 * cg;
            __half2 hp = __floats2half2_rn(c[nt][j0], c[nt][j0 + 1]);
            *(__half2*)&g_h16[(size_t)row * OUT_DIM + col] = hp;
            float2 la = *(float2*)&sAttL[col];
            float2 ra = *(float2*)&sAttR[col];
            int h = nt >> 1;
            sl[h] += c[nt][j0] * la.x + c[nt][j0 + 1] * la.y;
            sr[h] += c[nt][j0] * ra.x + c[nt][j0 + 1] * ra.y;
        }
#pragma unroll
        for (int h = 0; h < 4; h++) {
            sl[h] += __shfl_xor_sync(0xffffffffu, sl[h], 1);
            sr[h] += __shfl_xor_sync(0xffffffffu, sr[h], 1);
            sl[h] += __shfl_xor_sync(0xffffffffu, sl[h], 2);
            sr[h] += __shfl_xor_sync(0xffffffffu, sr[h], 2);
        }
        if (cg == 0) {
            *(float4*)&g_al[row * HEADS + wcol * 4] =
                make_float4(sl[0], sl[1], sl[2], sl[3]);
            *(float4*)&g_ar[row * HEADS + wcol * 4] =
                make_float4(sr[0], sr[1], sr[2], sr[3]);
        }
    }
}

// ------------------------------------------------------------------
// Gather: HALF-WARP per row (two independent chains per warp).
// Phase-1: 32 lanes compute alpha for 4 nbrs x 8 heads of row0,
// then row1; phase-2: lane l16 owns cols 8*l16..+7 of its half's
// row, 4 predicated LDG.128 per step. No atomics, no reductions.
// Padded CSR: beg = row<<6, end = deg[row].
// ------------------------------------------------------------------
__global__ void __launch_bounds__(256)
gather_kernel(const float* __restrict__ pos, float* __restrict__ out) {
    const int l   = threadIdx.x & 31;
    const int p   = l >> 4;         // half-warp -> row select
    const int l16 = l & 15;
    const int hd2 = l16 >> 1;       // head for this lane's 8 cols
    const int nb  = l >> 3;         // phase-1 neighbor slot (0..3)
    const int hp  = l & 7;          // phase-1 head (0..7)
    int warp = (blockIdx.x * blockDim.x + threadIdx.x) >> 5;
    if (warp >= N_NODES / 2) return;

    const int row0 = warp * 2;
    const int row1 = row0 + 1;
    const int myrow = p ? row1 : row0;

    int deg0 = min(g_deg[row0], CAP);
    int deg1 = min(g_deg[row1], CAP);
    const int beg0 = row0 << CAP_LOG;
    const int beg1 = row1 << CAP_LOG;
    float alr0 = g_al[row0 * HEADS + hp];
    float alr1 = g_al[row1 * HEADS + hp];

    float4 accA = make_float4(0.f, 0.f, 0.f, 0.f);
    float4 accB = make_float4(0.f, 0.f, 0.f, 0.f);
    float s = 0.f;
    const int steps = max(deg0, deg1);

    for (int base = 0; base < steps; base += 4) {
        int j = base + nb;
        int c0 = (j < deg0) ? g_csr_col[beg0 + j] : 0;
        int c1 = (j < deg1) ? g_csr_col[beg1 + j] : 0;
        float ar0 = g_ar[c0 * HEADS + hp];
        float ar1 = g_ar[c1 * HEADS + hp];
        float p0 = pos[c0];
        float p1 = pos[c1];

        float t0 = alr0 + ar0;
        t0 = (t0 >= 0.0f) ? t0 : NEG_SLOPE * t0;
        float a0 = (j < deg0) ? __expf(t0) * p0 : 0.0f;
        float t1 = alr1 + ar1;
        t1 = (t1 >= 0.0f) ? t1 : NEG_SLOPE * t1;
        float a1 = (j < deg1) ? __expf(t1) * p1 : 0.0f;

        float aq[4]; int cq[4];
#pragma unroll
        for (int k = 0; k < 4; k++) {
            float aa0 = __shfl_sync(0xffffffffu, a0, k * 8 + hd2);
            int   cc0 = __shfl_sync(0xffffffffu, c0, k * 8);
            float aa1 = __shfl_sync(0xffffffffu, a1, k * 8 + hd2);
            int   cc1 = __shfl_sync(0xffffffffu, c1, k * 8);
            aq[k] = p ? aa1 : aa0;
            cq[k] = p ? cc1 : cc0;
        }

        uint4 hv[4];
#pragma unroll
        for (int k = 0; k < 4; k++) {
            if (aq[k] != 0.0f)
                hv[k] = *(const uint4*)&g_h16[(size_t)cq[k] * OUT_DIM + 8 * l16];
            else
                hv[k] = make_uint4(0, 0, 0, 0);
        }
#pragma unroll
        for (int k = 0; k < 4; k++) {
            const __half2* h2p = (const __half2*)&hv[k];
            float2 f0 = __half22float2(h2p[0]);
            float2 f1 = __half22float2(h2p[1]);
            float2 f2 = __half22float2(h2p[2]);
            float2 f3 = __half22float2(h2p[3]);
            s += aq[k];
            accA.x += aq[k] * f0.x;
            accA.y += aq[k] * f0.y;
            accA.z += aq[k] * f1.x;
            accA.w += aq[k] * f1.y;
            accB.x += aq[k] * f2.x;
            accB.y += aq[k] * f2.y;
            accB.z += aq[k] * f3.x;
            accB.w += aq[k] * f3.y;
        }
    }

    int mydeg = p ? deg1 : deg0;
    float scale = (mydeg > 0) ? (1.0f / s + 1e-16f) : 0.0f;
    accA.x *= scale; accA.y *= scale; accA.z *= scale; accA.w *= scale;
    accB.x *= scale; accB.y *= scale; accB.z *= scale; accB.w *= scale;
    *(float4*)&out[(size_t)myrow * OUT_DIM + 8 * l16]     = accA;
    *(float4*)&out[(size_t)myrow * OUT_DIM + 8 * l16 + 4] = accB;
}

// ------------------------------------------------------------------
// Side stream + fork/join events (host-side resources, created once
// on the first non-capturing invocation).
// ------------------------------------------------------------------
struct SideStream {
    cudaStream_t s;
    cudaEvent_t fork, join;
    SideStream() {
        cudaStreamCreateWithFlags(&s, cudaStreamNonBlocking);
        cudaEventCreateWithFlags(&fork, cudaEventDisableTiming);
        cudaEventCreateWithFlags(&join, cudaEventDisableTiming);
    }
};
static SideStream& side() { static SideStream ss; return ss; }

extern "C" void kernel_launch(void* const* d_in, const int* in_sizes, int n_in,
                              void* d_out, int out_size) {
    const float* x   = (const float*)d_in[0];   // (N, 128)
    const int*   ei  = (const int*)d_in[1];     // (2, E)
    const float* pos = (const float*)d_in[2];   // (N,)
    const float* W   = (const float*)d_in[3];   // (128, 128)
    const float* att = (const float*)d_in[4];   // (1, 8, 32)
    float* out = (float*)d_out;

    SideStream& ss = side();

    // Fork: padded-CSR build on side stream; GEMM branch on origin.
    cudaEventRecord(ss.fork, 0);
    cudaStreamWaitEvent(ss.s, ss.fork, 0);

    void* degp = nullptr;
    cudaGetSymbolAddress(&degp, g_deg);
    cudaMemsetAsync(degp, 0, N_NODES * sizeof(int), ss.s);
    hist_kernel<<<1024, 256, 0, ss.s>>>(ei);
    scatter_kernel<<<1600, 256, 0, ss.s>>>(ei);
    cudaEventRecord(ss.join, ss.s);

    bfrag_build_kernel<<<16, 256>>>(W);
    const int GEMM_SMEM = 32768 + 64 * A_PITCH * 4 + 1024;   // 51200 B
    cudaFuncSetAttribute(gemm_kernel, cudaFuncAttributeMaxDynamicSharedMemorySize, GEMM_SMEM);
    gemm_kernel<<<GEMM_GROUPS, 256, GEMM_SMEM>>>(x, att);

    // Join, then fused softmax-normalized aggregation (atomic-free).
    cudaStreamWaitEvent(0, ss.join, 0);
    gather_kernel<<<(N_NODES / 2 + 7) / 8, 256>>>(pos, out);
}